// round 16
// baseline (speedup 1.0000x reference)
#include <cuda_runtime.h>
#include <cstdint>

// ============================================================================
// out[4096,1000] = core[4096,4096] @ weights[1000,4096]^T   (fp32)
//
// R16: warp-specialized producer. R13's GEMM (158.2us total) unchanged for
// warps 0-7; warp 8 (threads 256-287) is a dedicated pack warp that converts
// this CTA's 1/144 slice of each kt-group into the fragment-major scratch,
// racing ahead of consumption (~2.5K cyc/ktg vs ~6.2K compute pace) and
// publishing per-ktg counters. Compute warps use a named barrier (bar.sync
// 1,256) and gate stage-issue once per 4 phases on the counters. Register
// isolation: pack pressure lives in its own warp; compute regs unchanged.
// Counters self-reset (validated in R15) so graph replays are clean.
// ============================================================================

#define MDIM 4096
#define NDIM 1000
#define KDIM 4096

#define BM 256
#define BN 112
#define NTILES 9                      // 9*112 = 1008 >= 1000
#define BK 32
#define KTILES (KDIM / BK)            // 128
#define STAGES 4
#define THREADS 288                   // 8 compute warps + 1 pack warp
#define NU 7                          // u-extent per warp (56 cols / 8)
#define NCTA 144
#define NKTG 32

#define A_TILE_BYTES (BM * BK * 4)    // 32768
#define CHB (2 * NU * 4 * 32)         // B uint2-chunks per kt = 1792
#define B_TILE_BYTES (CHB * 8)        // 14336
#define STAGE_BYTES  (A_TILE_BYTES + B_TILE_BYTES)   // 47104
#define SMEM_BYTES   (STAGES * STAGE_BYTES)          // 188416

// per-ktg pack totals and per-CTA slices
#define TOTA 131072                   // uint4 per ktg (16 mtiles * 4 kt * 2048)
#define PERA 911                      // ceil(131072/144)
#define TOTB 64512                    // uint2 per ktg (9 ntiles * 4 kt * 1792)
#define PERB 448                      // 64512/144 exactly

// packed scratch:
//   A' = [16 mtiles][128 kt][2048 x 16B]
//   B' = [ 9 ntiles][128 kt][1792 x  8B]
__device__ uint4 g_Ap[16 * 128 * 2048];        // 64 MB
__device__ uint2 g_Bp[NTILES * 128 * CHB];     // ~16.5 MB
__device__ int   g_cnt[NKTG];                  // per-ktg completion counters (zero-init)
__device__ int   g_done;                       // CTA completion counter (zero-init)

// ---------------------------------------------------------------------------
__device__ __forceinline__ uint32_t smem_u32(const void* p) {
    uint32_t a;
    asm("{ .reg .u64 t; cvta.to.shared.u64 t, %1; cvt.u32.u64 %0, t; }" : "=r"(a) : "l"(p));
    return a;
}

__device__ __forceinline__ void cp16(uint32_t dst, const void* src) {
    asm volatile("cp.async.cg.shared.global [%0], [%1], 16;"
                 :: "r"(dst), "l"(src) : "memory");
}
#define CP_COMMIT() asm volatile("cp.async.commit_group;" ::: "memory")
#define CP_WAIT1()  asm volatile("cp.async.wait_group 1;"  ::: "memory")
#define CP_WAIT2()  asm volatile("cp.async.wait_group 2;"  ::: "memory")

// named barrier for the 8 compute warps only (pack warp never joins)
#define NB() asm volatile("bar.sync 1, 256;" ::: "memory")

__device__ __forceinline__ uint32_t f2tf(float f) {
    uint32_t r;
    asm("cvt.rna.tf32.f32 %0, %1;" : "=r"(r) : "f"(f));
    return r;
}

__device__ __forceinline__ void mma_tf32(float c[4],
                                         const uint32_t a[4], const uint32_t b[2]) {
    asm volatile(
        "mma.sync.aligned.m16n8k8.row.col.f32.tf32.tf32.f32 "
        "{%0,%1,%2,%3}, {%4,%5,%6,%7}, {%8,%9}, {%0,%1,%2,%3};"
        : "+f"(c[0]), "+f"(c[1]), "+f"(c[2]), "+f"(c[3])
        : "r"(a[0]), "r"(a[1]), "r"(a[2]), "r"(a[3]), "r"(b[0]), "r"(b[1]));
}

// Bounded acquire-spin until ktg g is fully packed by all NCTA CTAs.
// Bounded so tool-forced anomalies terminate; in normal runs the producer
// warps are co-resident and always publish.
__device__ __forceinline__ void wait_cnt(int g) {
    const int* p = g_cnt + g;
    int v;
    unsigned guard = 0;
    do {
        asm volatile("ld.acquire.gpu.b32 %0, [%1];" : "=r"(v) : "l"(p) : "memory");
    } while (v < NCTA && ++guard < (1u << 20));
}

// ---------------------------------------------------------------------------
// Producer-warp pack: this CTA's 1/144 slice of kt-group g, executed by 32
// threads (lane = tid-256). Layouts identical to R13's pack (validated).
// ---------------------------------------------------------------------------
__device__ __forceinline__ void pack_slice_w(const float* __restrict__ A,
                                             const float* __restrict__ B,
                                             int g, int cta, int lane) {
    // ---- A slice: PERA=911 uint4, 29 iterations of 32 ----
    const uint32_t abase = (uint32_t)cta * PERA;
    #pragma unroll 4
    for (int it = 0; it < 29; it++) {
        const uint32_t off = (uint32_t)(it * 32 + lane);
        const uint32_t idx = abase + off;
        if (off < PERA && idx < TOTA) {
            const uint32_t mt    = idx >> 13;
            const uint32_t rem   = idx & 8191u;
            const uint32_t ktl   = rem >> 11;
            const uint32_t chunk = rem & 2047u;
            const uint32_t ln    = chunk & 31u;
            const uint32_t blk   = chunk >> 5;
            const uint32_t ks    = blk & 3u;
            const uint32_t t     = (blk >> 2) & 3u;
            const uint32_t wm    = blk >> 4;
            const uint32_t r  = mt * 256 + wm * 64 + t * 16 + (ln >> 2);
            const uint32_t kt = g * 4 + ktl;
            const uint32_t c  = kt * 32 + ks * 8 + (ln & 3);
            const float* p = A + (size_t)r * KDIM + c;
            uint4 v;
            v.x = f2tf(p[0]);
            v.y = f2tf(p[(size_t)8 * KDIM]);
            v.z = f2tf(p[4]);
            v.w = f2tf(p[(size_t)8 * KDIM + 4]);
            g_Ap[(size_t)(mt * 128 + kt) * 2048 + chunk] = v;
        }
    }
    // ---- B slice: PERB=448 uint2, 14 iterations of 32 ----
    const uint32_t bbase = (uint32_t)cta * PERB;
    #pragma unroll 4
    for (int it = 0; it < 14; it++) {
        const uint32_t idx   = bbase + (uint32_t)(it * 32 + lane);
        const uint32_t nt    = idx / (4 * CHB);
        const uint32_t rem   = idx - nt * (4 * CHB);
        const uint32_t ktl   = rem / CHB;
        const uint32_t chunk = rem - ktl * CHB;
        const uint32_t ln    = chunk & 31u;
        const uint32_t blk   = chunk >> 5;
        const uint32_t ks    = blk & 3u;
        const uint32_t uw    = blk >> 2;
        const uint32_t u     = uw % NU;
        const uint32_t wn    = uw / NU;
        const uint32_t n  = nt * BN + wn * 56 + u * 8 + (ln >> 2);
        const uint32_t kt = g * 4 + ktl;
        const uint32_t c  = kt * 32 + ks * 8 + (ln & 3);
        uint2 v = make_uint2(0u, 0u);
        if (n < NDIM) {
            const float* p = B + (size_t)n * KDIM + c;
            v.x = f2tf(p[0]);
            v.y = f2tf(p[4]);
        }
        g_Bp[(size_t)(nt * 128 + kt) * CHB + chunk] = v;
    }
}

// ---------------------------------------------------------------------------
__global__ void __launch_bounds__(THREADS, 1)
tol_gemm_tf32(const float* __restrict__ Ain,
              const float* __restrict__ Bin,
              float* __restrict__ C) {         // [4096, 1000]
    extern __shared__ char smem[];
    const int tid  = threadIdx.x;
    const int wid  = tid >> 5;
    const int lane = tid & 31;

    const int mtile = blockIdx.y;
    const int ntile = blockIdx.x;
    const int m0 = mtile * BM;
    const int n0 = ntile * BN;
    const int cta = mtile * NTILES + ntile;    // 0..143

    // ======================= PRODUCER WARP (wid 8) =========================
    if (wid == 8) {
        for (int g = 0; g < NKTG; g++) {
            pack_slice_w(Ain, Bin, g, cta, lane);
            __threadfence();
            __syncwarp();
            if (lane == 0) atomicAdd(&g_cnt[g], 1);
        }
        return;   // producer done; compute warps proceed independently
    }

    // ======================= COMPUTE WARPS (wid 0-7) =======================
    const int warp_m = wid >> 1;     // 0..3
    const int warp_n = wid & 1;      // 0..1

    const uint32_t sb = smem_u32(smem);

#define ISSUE_STAGE(kt_, s_) do {                                                \
        const uint32_t soff = (uint32_t)(s_) * STAGE_BYTES;                      \
        const uint4* asrc = g_Ap + ((size_t)(mtile * KTILES + (kt_))) * 2048;    \
        const uint2* bsrc = g_Bp + ((size_t)(ntile * KTILES + (kt_))) * CHB;     \
        _Pragma("unroll")                                                        \
        for (int i = 0; i < 8; i++)                                              \
            cp16(sb + soff + (uint32_t)(tid + i * 256) * 16,                     \
                 asrc + tid + i * 256);                                          \
        _Pragma("unroll")                                                        \
        for (int i = 0; i < 3; i++)                                              \
            cp16(sb + soff + A_TILE_BYTES + (uint32_t)(tid + i * 256) * 16,      \
                 bsrc + (tid + i * 256) * 2);                                    \
        if (tid < 128)                                                           \
            cp16(sb + soff + A_TILE_BYTES + (uint32_t)(tid + 768) * 16,          \
                 bsrc + (tid + 768) * 2);                                        \
    } while (0)

    float acc[4][NU][4];
    #pragma unroll
    for (int t = 0; t < 4; t++)
        #pragma unroll
        for (int u = 0; u < NU; u++)
            #pragma unroll
            for (int i = 0; i < 4; i++)
                acc[t][u][i] = 0.0f;

    // prologue: wait for ktg0 (covers kt 0..3), then fill 3 stages
    if (tid == 0) wait_cnt(0);
    NB();
    #pragma unroll
    for (int p = 0; p < STAGES - 1; p++) {
        ISSUE_STAGE(p, p);
        CP_COMMIT();
    }

    // fragment double buffers
    uint32_t af[2][4][4];
    uint32_t bf[2][NU][2];

#define LOAD_FRAG(buf, aS, bS, ksv) do {                                         \
        _Pragma("unroll")                                                        \
        for (int t = 0; t < 4; t++) {                                            \
            uint4 v = (aS)[((warp_m * 4 + t) * 4 + (ksv)) * 32 + lane];          \
            af[buf][t][0] = v.x; af[buf][t][1] = v.y;                            \
            af[buf][t][2] = v.z; af[buf][t][3] = v.w;                            \
        }                                                                        \
        _Pragma("unroll")                                                        \
        for (int u = 0; u < NU; u++) {                                           \
            uint2 w = (bS)[((warp_n * NU + u) * 4 + (ksv)) * 32 + lane];         \
            bf[buf][u][0] = w.x; bf[buf][u][1] = w.y;                            \
        }                                                                        \
    } while (0)

#define MMA_ALL(buf) do {                                                        \
        _Pragma("unroll")                                                        \
        for (int t = 0; t < 4; t++)                                              \
            _Pragma("unroll")                                                    \
            for (int u = 0; u < NU; u++)                                         \
                mma_tf32(acc[t][u], af[buf][t], bf[buf][u]);                     \
    } while (0)

#define STAGE_A(s_) reinterpret_cast<const uint4*>(smem + (s_) * STAGE_BYTES)
#define STAGE_B(s_) reinterpret_cast<const uint2*>(smem + (s_) * STAGE_BYTES + A_TILE_BYTES)

    // preload buf0 = frag(kt=0, ks=0) from stage 0
    CP_WAIT2();
    NB();
    LOAD_FRAG(0, STAGE_A(0), STAGE_B(0), 0);

    // One pipeline phase at compile-time stage S. GATE=1 in the phase whose
    // refill crosses into a new ktg: tid0 acquire-spins on that counter
    // (monotone; already-set in steady state) before the named barrier.
#define PHASE(S, kt_, GATE) do {                                                 \
        CP_WAIT1();                                                              \
        const int kn = (kt_) + STAGES - 1;                                       \
        if ((GATE) && kn < KTILES && tid == 0) wait_cnt(kn >> 2);                \
        NB();                                                                    \
        if (kn < KTILES) ISSUE_STAGE(kn, ((S) + STAGES - 1) & 3);                \
        CP_COMMIT();                                                             \
        const uint4* aS = STAGE_A(S);                                            \
        const uint2* bS = STAGE_B(S);                                            \
        const uint4* aN = STAGE_A(((S) + 1) & 3);                                \
        const uint2* bN = STAGE_B(((S) + 1) & 3);                                \
        LOAD_FRAG(1, aS, bS, 1);  MMA_ALL(0);                                    \
        LOAD_FRAG(0, aS, bS, 2);  MMA_ALL(1);                                    \
        LOAD_FRAG(1, aS, bS, 3);  MMA_ALL(0);                                    \
        LOAD_FRAG(0, aN, bN, 0);  MMA_ALL(1);                                    \
    } while (0)

    for (int kt = 0; kt < KTILES; kt += 4) {
        PHASE(0, kt,     0);
        PHASE(1, kt + 1, 1);   // kn = kt+4 -> first kt of ktg (kt>>2)+1
        PHASE(2, kt + 2, 0);
        PHASE(3, kt + 3, 0);
    }

    // ---- epilogue: each warp writes its 64x56 region, guard N edge ----
    #pragma unroll
    for (int t = 0; t < 4; t++) {
        const int gr = m0 + warp_m * 64 + t * 16 + (lane >> 2);
        #pragma unroll
        for (int u = 0; u < NU; u++) {
            const int gc = n0 + warp_n * 56 + u * 8 + (lane & 3) * 2;
            if (gc < NDIM) {   // NDIM even; float2 never straddles the edge
                float2 v0 = make_float2(acc[t][u][0], acc[t][u][1]);
                float2 v1 = make_float2(acc[t][u][2], acc[t][u][3]);
                *reinterpret_cast<float2*>(C + (size_t)gr * NDIM + gc) = v0;
                *reinterpret_cast<float2*>(C + (size_t)(gr + 8) * NDIM + gc) = v1;
            }
        }
    }

    // ---- self-reset counters for the next (graph-replayed) launch ----
    // tid0 arrives here only after passing every gate; the LAST CTA to
    // arrive zeroes the counters (validated scheme from R15).
    if (tid == 0) {
        const int v = atomicAdd(&g_done, 1);
        if (v == NCTA - 1) {
            #pragma unroll
            for (int i = 0; i < NKTG; i++) g_cnt[i] = 0;
            __threadfence();
            g_done = 0;
        }
    }
}

// ---------------------------------------------------------------------------
extern "C" void kernel_launch(void* const* d_in, const int* in_sizes, int n_in,
                              void* d_out, int out_size) {
    const float* core = (const float*)d_in[0];   // [4096, 16,16,16] = [4096,4096]
    const float* wts  = (const float*)d_in[1];   // [1000, 4096]
    float* out = (float*)d_out;                  // [4096, 1000]

    cudaFuncSetAttribute(tol_gemm_tf32,
                         cudaFuncAttributeMaxDynamicSharedMemorySize, SMEM_BYTES);

    dim3 grid(NTILES, 16, 1);   // 9 x 16 = 144 CTAs = one co-resident wave
    tol_gemm_tf32<<<grid, THREADS, SMEM_BYTES>>>(core, wts, out);
}

// round 17
// speedup vs baseline: 4.4293x; 4.4293x over previous
#include <cuda_runtime.h>
#include <cstdint>

// ============================================================================
// out[4096,1000] = core[4096,4096] @ weights[1000,4096]^T   (fp32)
//
// R17 = R13 (best verified: 158.2us) with one low-risk pack tweak.
// Overlap experiments R14/R15/R16 all regressed (SM starvation / register
// pressure / uniform-regfile spills) and are abandoned.
//  - GEMM: R13 byte-for-byte. BM256xBN112, 144 CTAs = 1 wave, per-kt commit
//    groups, per-kt barrier, 4-stage cp.async, cross-phase ks0 prefetch.
//  - Pack: per-thread kt coverage 4 -> 8 (MLP ~16 -> ~32) to lift the
//    latency-bound pack (HBM was only 49%) toward its bandwidth floor.
// ============================================================================

#define MDIM 4096
#define NDIM 1000
#define KDIM 4096

#define BM 256
#define BN 112
#define NTILES 9                      // 9*112 = 1008 >= 1000
#define BK 32
#define KTILES (KDIM / BK)            // 128
#define STAGES 4
#define THREADS 256
#define NU 7                          // u-extent per warp (56 cols / 8)

#define A_TILE_BYTES (BM * BK * 4)    // 32768
#define CHB (2 * NU * 4 * 32)         // B uint2-chunks per kt = 1792
#define B_TILE_BYTES (CHB * 8)        // 14336
#define STAGE_BYTES  (A_TILE_BYTES + B_TILE_BYTES)   // 47104
#define SMEM_BYTES   (STAGES * STAGE_BYTES)          // 188416

// packed scratch:
//   A' = [16 mtiles][128 kt][2048 x 16B]
//   B' = [ 9 ntiles][128 kt][1792 x  8B]
__device__ uint4 g_Ap[16 * 128 * 2048];        // 64 MB
__device__ uint2 g_Bp[NTILES * 128 * CHB];     // ~16.5 MB

// ---------------------------------------------------------------------------
__device__ __forceinline__ uint32_t smem_u32(const void* p) {
    uint32_t a;
    asm("{ .reg .u64 t; cvta.to.shared.u64 t, %1; cvt.u32.u64 %0, t; }" : "=r"(a) : "l"(p));
    return a;
}

__device__ __forceinline__ void cp16(uint32_t dst, const void* src) {
    asm volatile("cp.async.cg.shared.global [%0], [%1], 16;"
                 :: "r"(dst), "l"(src) : "memory");
}
#define CP_COMMIT() asm volatile("cp.async.commit_group;" ::: "memory")
#define CP_WAIT1()  asm volatile("cp.async.wait_group 1;"  ::: "memory")
#define CP_WAIT2()  asm volatile("cp.async.wait_group 2;"  ::: "memory")

__device__ __forceinline__ uint32_t f2tf(float f) {
    uint32_t r;
    asm("cvt.rna.tf32.f32 %0, %1;" : "=r"(r) : "f"(f));
    return r;
}

__device__ __forceinline__ void mma_tf32(float c[4],
                                         const uint32_t a[4], const uint32_t b[2]) {
    asm volatile(
        "mma.sync.aligned.m16n8k8.row.col.f32.tf32.tf32.f32 "
        "{%0,%1,%2,%3}, {%4,%5,%6,%7}, {%8,%9}, {%0,%1,%2,%3};"
        : "+f"(c[0]), "+f"(c[1]), "+f"(c[2]), "+f"(c[3])
        : "r"(a[0]), "r"(a[1]), "r"(a[2]), "r"(a[3]), "r"(b[0]), "r"(b[1]));
}

// ---------------------------------------------------------------------------
// Fused pack kernel, 8 kt per thread (MLP ~32).
//   A chunk ((wm*4+t)*4+ks)*32+lane -> 16B quad {A[r,c],A[r+8,c],A[r,c+4],A[r+8,c+4]}
//   B chunk ((wn*7+u)*4+ks)*32+lane -> 8B pair {B[n,c],B[n,c+4]}, n>=1000 zeroed
// Blocks [0,2048): A.  idx = bid*256+tid in [0, 2^19):
//   mtile = idx>>15, ktg = (idx>>11)&15 (16 groups of 8 kt), chunk = idx&2047.
// Blocks [2048,3056): B.  idx in [0, 258048):
//   chunk = idx%1792, rest = idx/1792 in [0,144), ktg = rest&15, ntile = rest>>4.
// ---------------------------------------------------------------------------
__global__ void __launch_bounds__(256) pack_ab_kernel(const float* __restrict__ A,
                                                      const float* __restrict__ B) {
    const uint32_t bid = blockIdx.x;
    const uint32_t tidl = threadIdx.x;
    if (bid < 2048) {
        const uint32_t idx = bid * 256u + tidl;        // [0, 2^19)
        const uint32_t mtile = idx >> 15;              // 16 mtiles
        const uint32_t ktg   = (idx >> 11) & 15u;      // 16 kt-groups of 8
        const uint32_t chunk = idx & 2047u;
        const uint32_t lane  = chunk & 31u;
        const uint32_t blk   = chunk >> 5;
        const uint32_t ks    = blk & 3u;
        const uint32_t t     = (blk >> 2) & 3u;
        const uint32_t wm    = blk >> 4;
        const uint32_t r = mtile * 256 + wm * 64 + t * 16 + (lane >> 2);
        const float* rowp = A + (size_t)r * KDIM;
        #pragma unroll
        for (int j = 0; j < 8; j++) {
            const uint32_t kt = ktg * 8 + j;
            const uint32_t c  = kt * 32 + ks * 8 + (lane & 3);
            const float* p = rowp + c;
            uint4 v;
            v.x = f2tf(p[0]);
            v.y = f2tf(p[(size_t)8 * KDIM]);
            v.z = f2tf(p[4]);
            v.w = f2tf(p[(size_t)8 * KDIM + 4]);
            g_Ap[(size_t)(mtile * 128 + kt) * 2048 + chunk] = v;
        }
    } else {
        const uint32_t idx   = (bid - 2048u) * 256u + tidl;   // [0, 258048)
        const uint32_t chunk = idx % CHB;                     // 0..1791
        const uint32_t rest  = idx / CHB;                     // 0..143
        const uint32_t ktg   = rest & 15u;                    // 16 kt-groups of 8
        const uint32_t ntile = rest >> 4;                     // 0..8
        const uint32_t lane  = chunk & 31u;
        const uint32_t blk   = chunk >> 5;                    // 0..55
        const uint32_t ks    = blk & 3u;
        const uint32_t uw    = blk >> 2;                      // 0..13 = wn*7+u
        const uint32_t u     = uw % NU;
        const uint32_t wn    = uw / NU;
        const uint32_t n = ntile * BN + wn * 56 + u * 8 + (lane >> 2);
        const float* rowp = B + (size_t)n * KDIM;
        #pragma unroll
        for (int j = 0; j < 8; j++) {
            const uint32_t kt = ktg * 8 + j;
            const uint32_t c  = kt * 32 + ks * 8 + (lane & 3);
            uint2 v = make_uint2(0u, 0u);
            if (n < NDIM) {
                const float* p = rowp + c;
                v.x = f2tf(p[0]);
                v.y = f2tf(p[4]);
            }
            g_Bp[(size_t)(ntile * 128 + kt) * CHB + chunk] = v;
        }
    }
}

// ---------------------------------------------------------------------------
// GEMM: R13 byte-for-byte.
// ---------------------------------------------------------------------------
__global__ void __launch_bounds__(THREADS, 1)
tol_gemm_tf32(float* __restrict__ C) {         // [4096, 1000]
    extern __shared__ char smem[];
    const int tid  = threadIdx.x;
    const int wid  = tid >> 5;
    const int lane = tid & 31;

    const int mtile = blockIdx.y;
    const int ntile = blockIdx.x;
    const int m0 = mtile * BM;
    const int n0 = ntile * BN;

    const int warp_m = wid >> 1;     // 0..3
    const int warp_n = wid & 1;      // 0..1

    const uint32_t sb = smem_u32(smem);

#define ISSUE_STAGE(kt_, s_) do {                                                \
        const uint32_t soff = (uint32_t)(s_) * STAGE_BYTES;                      \
        const uint4* asrc = g_Ap + ((size_t)(mtile * KTILES + (kt_))) * 2048;    \
        const uint2* bsrc = g_Bp + ((size_t)(ntile * KTILES + (kt_))) * CHB;     \
        _Pragma("unroll")                                                        \
        for (int i = 0; i < 8; i++)                                              \
            cp16(sb + soff + (uint32_t)(tid + i * 256) * 16,                     \
                 asrc + tid + i * 256);                                          \
        _Pragma("unroll")                                                        \
        for (int i = 0; i < 3; i++)                                              \
            cp16(sb + soff + A_TILE_BYTES + (uint32_t)(tid + i * 256) * 16,      \
                 bsrc + (tid + i * 256) * 2);                                    \
        if (tid < 128)                                                           \
            cp16(sb + soff + A_TILE_BYTES + (uint32_t)(tid + 768) * 16,          \
                 bsrc + (tid + 768) * 2);                                        \
    } while (0)

    float acc[4][NU][4];
    #pragma unroll
    for (int t = 0; t < 4; t++)
        #pragma unroll
        for (int u = 0; u < NU; u++)
            #pragma unroll
            for (int i = 0; i < 4; i++)
                acc[t][u][i] = 0.0f;

    // prologue: fill STAGES-1 = 3 stages
    #pragma unroll
    for (int p = 0; p < STAGES - 1; p++) {
        ISSUE_STAGE(p, p);
        CP_COMMIT();
    }

    // fragment double buffers
    uint32_t af[2][4][4];
    uint32_t bf[2][NU][2];

#define LOAD_FRAG(buf, aS, bS, ksv) do {                                         \
        _Pragma("unroll")                                                        \
        for (int t = 0; t < 4; t++) {                                            \
            uint4 v = (aS)[((warp_m * 4 + t) * 4 + (ksv)) * 32 + lane];          \
            af[buf][t][0] = v.x; af[buf][t][1] = v.y;                            \
            af[buf][t][2] = v.z; af[buf][t][3] = v.w;                            \
        }                                                                        \
        _Pragma("unroll")                                                        \
        for (int u = 0; u < NU; u++) {                                           \
            uint2 w = (bS)[((warp_n * NU + u) * 4 + (ksv)) * 32 + lane];         \
            bf[buf][u][0] = w.x; bf[buf][u][1] = w.y;                            \
        }                                                                        \
    } while (0)

#define MMA_ALL(buf) do {                                                        \
        _Pragma("unroll")                                                        \
        for (int t = 0; t < 4; t++)                                              \
            _Pragma("unroll")                                                    \
            for (int u = 0; u < NU; u++)                                         \
                mma_tf32(acc[t][u], af[buf][t], bf[buf][u]);                     \
    } while (0)

#define STAGE_A(s_) reinterpret_cast<const uint4*>(smem + (s_) * STAGE_BYTES)
#define STAGE_B(s_) reinterpret_cast<const uint2*>(smem + (s_) * STAGE_BYTES + A_TILE_BYTES)

    // preload buf0 = frag(kt=0, ks=0) from stage 0
    CP_WAIT2();
    __syncthreads();
    LOAD_FRAG(0, STAGE_A(0), STAGE_B(0), 0);

#define PHASE(S, kt_) do {                                                       \
        CP_WAIT1();                                                              \
        __syncthreads();                                                         \
        const int kn = (kt_) + STAGES - 1;                                       \
        if (kn < KTILES) ISSUE_STAGE(kn, ((S) + STAGES - 1) & 3);                \
        CP_COMMIT();                                                             \
        const uint4* aS = STAGE_A(S);                                            \
        const uint2* bS = STAGE_B(S);                                            \
        const uint4* aN = STAGE_A(((S) + 1) & 3);                                \
        const uint2* bN = STAGE_B(((S) + 1) & 3);                                \
        LOAD_FRAG(1, aS, bS, 1);  MMA_ALL(0);                                    \
        LOAD_FRAG(0, aS, bS, 2);  MMA_ALL(1);                                    \
        LOAD_FRAG(1, aS, bS, 3);  MMA_ALL(0);                                    \
        LOAD_FRAG(0, aN, bN, 0);  MMA_ALL(1);                                    \
    } while (0)

    for (int kt = 0; kt < KTILES; kt += 4) {
        PHASE(0, kt);
        PHASE(1, kt + 1);
        PHASE(2, kt + 2);
        PHASE(3, kt + 3);
    }

    // ---- epilogue: each warp writes its 64x56 region, guard N edge ----
    #pragma unroll
    for (int t = 0; t < 4; t++) {
        const int gr = m0 + warp_m * 64 + t * 16 + (lane >> 2);
        #pragma unroll
        for (int u = 0; u < NU; u++) {
            const int gc = n0 + warp_n * 56 + u * 8 + (lane & 3) * 2;
            if (gc < NDIM) {   // NDIM even; float2 never straddles the edge
                float2 v0 = make_float2(acc[t][u][0], acc[t][u][1]);
                float2 v1 = make_float2(acc[t][u][2], acc[t][u][3]);
                *reinterpret_cast<float2*>(C + (size_t)gr * NDIM + gc) = v0;
                *reinterpret_cast<float2*>(C + (size_t)(gr + 8) * NDIM + gc) = v1;
            }
        }
    }
}

// ---------------------------------------------------------------------------
extern "C" void kernel_launch(void* const* d_in, const int* in_sizes, int n_in,
                              void* d_out, int out_size) {
    const float* core = (const float*)d_in[0];   // [4096, 16,16,16] = [4096,4096]
    const float* wts  = (const float*)d_in[1];   // [1000, 4096]
    float* out = (float*)d_out;                  // [4096, 1000]

    // fused pack prepass: 2048 A-blocks + 1008 B-blocks
    pack_ab_kernel<<<3056, 256>>>(core, wts);

    cudaFuncSetAttribute(tol_gemm_tf32,
                         cudaFuncAttributeMaxDynamicSharedMemorySize, SMEM_BYTES);

    dim3 grid(NTILES, 16, 1);   // 9 x 16 = 144 CTAs = one wave on 148 SMs
    tol_gemm_tf32<<<grid, THREADS, SMEM_BYTES>>>(out);
}